// round 10
// baseline (speedup 1.0000x reference)
#include <cuda_runtime.h>
#include <cuda_fp16.h>
#include <cstdint>
#include <math.h>

// SparseGate: B=16384, D=2048, E=64, K=2
// mma.sync.m16n8k16.f16 (f32 accum), 3-pass hi/lo split (hh+hl+lh).
// W pre-scaled x1024 so lo-half stays fp16-normal; epilogue undoes scale.
// 16 warps = 4(wm) x 2(wn) x 2(kg split-K), warp tile 32x64 (kc fixed = kg):
// fragment traffic 96KB/ktile (vs 128KB at 4x4). Register-pipelined: staging
// for kt+1/kt+2 issues under the MMA bursts; 1 barrier per ktile.

#define BDIM 2048
#define EN   64
#define NN   128          // gate(64) || noise(64)
#define BM   128
#define BK   32
#define NKT  (BDIM / BK)  // 64
#define WSCALE 1024.0f
#define WSCALE_INV 0.0009765625f
#define LLD  131

// stage layout (bytes): A-hi [128 x 64B SW64], A-lo same, W [128 n x 192B]
#define ST_AH 0
#define ST_AL 8192
#define ST_W  16384
#define STAGE 40960
#define SMEM_TOTAL (3 * STAGE)   // 122880 (>= 128*131*4 = 67072 for logits)

#define SW64(o) ((o) ^ (((o) >> 3) & 0x30))

// Pre-split W records: per (ktile, n, kc, qc) a 16B record
// { wh[2qc],wh[2qc+1], wh[2qc+8],wh[2qc+9], wl[same 4] } (fp16)
__device__ uint4 g_Wc[(size_t)NKT * 1024];   // 64 ktiles * 128 n * 8 records

__device__ __forceinline__ uint32_t smem_u32(const void* p) {
    uint32_t a;
    asm("{ .reg .u64 t; cvta.to.shared.u64 t, %1; cvt.u32.u64 %0, t; }" : "=r"(a) : "l"(p));
    return a;
}
__device__ __forceinline__ void cp16(uint32_t saddr, const void* g) {
    asm volatile("cp.async.cg.shared.global [%0], [%1], 16;" :: "r"(saddr), "l"(g));
}
__device__ __forceinline__ void ldm4(uint32_t* r, uint32_t addr) {
    asm volatile("ldmatrix.sync.aligned.m8n8.x4.shared.b16 {%0,%1,%2,%3}, [%4];"
                 : "=r"(r[0]), "=r"(r[1]), "=r"(r[2]), "=r"(r[3]) : "r"(addr));
}
__device__ __forceinline__ void lds128(uint32_t* r, uint32_t addr) {
    asm volatile("ld.shared.v4.b32 {%0,%1,%2,%3}, [%4];"
                 : "=r"(r[0]), "=r"(r[1]), "=r"(r[2]), "=r"(r[3]) : "r"(addr));
}
__device__ __forceinline__ void sts128(uint32_t addr, uint32_t a, uint32_t b,
                                       uint32_t c, uint32_t d) {
    asm volatile("st.shared.v4.b32 [%0], {%1,%2,%3,%4};"
                 :: "r"(addr), "r"(a), "r"(b), "r"(c), "r"(d) : "memory");
}
__device__ __forceinline__ void mma16(float* c, const uint32_t* a, uint32_t b0, uint32_t b1) {
    asm volatile("mma.sync.aligned.m16n8k16.row.col.f32.f16.f16.f32 "
                 "{%0,%1,%2,%3},{%4,%5,%6,%7},{%8,%9},{%0,%1,%2,%3};\n"
                 : "+f"(c[0]), "+f"(c[1]), "+f"(c[2]), "+f"(c[3])
                 : "r"(a[0]), "r"(a[1]), "r"(a[2]), "r"(a[3]), "r"(b0), "r"(b1));
}
__device__ __forceinline__ uint32_t pack2(float a, float b, float& ra, float& rb) {
    __half ha = __float2half_rn(a), hb = __float2half_rn(b);
    ra = a - __half2float(ha);
    rb = b - __half2float(hb);
    __half2 p = __halves2half2(ha, hb);
    return *reinterpret_cast<uint32_t*>(&p);
}

// ---------------- W pre-split ----------------
__global__ void __launch_bounds__(256) split_w_kernel(const float* __restrict__ gw,
                                                      const float* __restrict__ nw) {
    int i = blockIdx.x * blockDim.x + threadIdx.x;   // (n, kt, kc, qc)
    if (i >= NN * NKT * 8) return;
    int qc = i & 3, kc = (i >> 2) & 1, kt = (i >> 3) & 63, n = i >> 9;
    const float* src = (n < EN) ? (gw + (size_t)n * BDIM) : (nw + (size_t)(n - EN) * BDIM);
    int kb = kt * BK + kc * 16 + 2 * qc;
    float w0 = src[kb] * WSCALE,     w1 = src[kb + 1] * WSCALE;
    float w2 = src[kb + 8] * WSCALE, w3 = src[kb + 9] * WSCALE;
    float r0, r1, r2, r3;
    uint32_t h01 = pack2(w0, w1, r0, r1);
    uint32_t h23 = pack2(w2, w3, r2, r3);
    float d0, d1;
    uint32_t l01 = pack2(r0, r1, d0, d1);
    uint32_t l23 = pack2(r2, r3, d0, d1);
    g_Wc[(size_t)kt * 1024 + n * 8 + kc * 4 + qc] = make_uint4(h01, h23, l01, l23);
}

// ---------------- fused GEMM + gate ----------------
__global__ void __launch_bounds__(512, 1)
gate_kernel(const float* __restrict__ x, const float* __restrict__ noise,
            float* __restrict__ out) {
    extern __shared__ char smem[];
    const uint32_t sb = smem_u32(smem);
    const int tid  = threadIdx.x;
    const int wid  = tid >> 5, lane = tid & 31;
    const int gr   = lane >> 2, qc = lane & 3;
    const int wm   = wid & 3;          // 4 row groups of 32
    const int wn   = (wid >> 2) & 1;   // 2 col groups of 64
    const int kg   = wid >> 3;         // split-K half (fixed kc for this warp)
    const int m0   = blockIdx.x * BM;

    // A staging: this thread stores row ar, k-octet ao (8 fp32 -> 16B fp16)
    const int ar = tid & 127, ao = tid >> 7;
    const float* xrow = x + (size_t)(m0 + ar) * BDIM + ao * 8;
    const uint32_t swoA = SW64((uint32_t)(ar * 64 + ao * 16));

    // ldmatrix addresses (tile-relative, SW64). kg selects the 32B k-half;
    // bit5 of the pre-swizzle base is 0 and +32 leaves XOR source bits [7:9)
    // unchanged, so SW64(base + kg*32) = SW64(base) ^ (kg*32).
    const int lrow = lane & 15, lko = lane >> 4;
    uint32_t aoff[2];
#pragma unroll
    for (int tm = 0; tm < 2; tm++)
        aoff[tm] = SW64((uint32_t)((32 * wm + 16 * tm + lrow) * 64 + lko * 16))
                   ^ (uint32_t)(kg * 32);
    // B fragment base: n*192 + kg*64 + qc*16; n-tile t adds 1536
    const uint32_t wbase = (uint32_t)((64 * wn + gr) * 192 + kg * 64 + qc * 16);

    float acc[2][8][4];
#pragma unroll
    for (int a = 0; a < 2; a++)
#pragma unroll
        for (int b = 0; b < 8; b++)
#pragma unroll
            for (int c = 0; c < 4; c++) acc[a][b][c] = 0.f;

    auto copyW = [&](int kt, uint32_t stage) {
#pragma unroll
        for (int j = 0; j < 2; j++) {
            int id = tid + j * 512;                        // 1024 records
            cp16(stage + ST_W + (id >> 3) * 192 + (id & 7) * 16,
                 (const void*)(g_Wc + (size_t)kt * 1024 + id));
        }
    };
    auto stsA = [&](uint32_t stage, float4 v0, float4 v1) {
        float r0, r1, r2, r3, r4, r5, r6, r7;
        uint32_t h0 = pack2(v0.x, v0.y, r0, r1);
        uint32_t h1 = pack2(v0.z, v0.w, r2, r3);
        uint32_t h2 = pack2(v1.x, v1.y, r4, r5);
        uint32_t h3 = pack2(v1.z, v1.w, r6, r7);
        float d0, d1;
        uint32_t l0 = pack2(r0, r1, d0, d1);
        uint32_t l1 = pack2(r2, r3, d0, d1);
        uint32_t l2 = pack2(r4, r5, d0, d1);
        uint32_t l3 = pack2(r6, r7, d0, d1);
        sts128(stage + ST_AH + swoA, h0, h1, h2, h3);
        sts128(stage + ST_AL + swoA, l0, l1, l2, l3);
    };

    // fragment buffers (single A buffer; B in halves of 4 n-tiles)
    uint32_t ah[2][4], al[2][4];
    uint32_t bh[4][2], bl[4][2];

#define LDM_A(stg)                                   \
    do {                                             \
        ldm4(ah[0], (stg) + ST_AH + aoff[0]);        \
        ldm4(ah[1], (stg) + ST_AH + aoff[1]);        \
        ldm4(al[0], (stg) + ST_AL + aoff[0]);        \
        ldm4(al[1], (stg) + ST_AL + aoff[1]);        \
    } while (0)
#define LDS_B(stg, half)                                                      \
    do {                                                                      \
        _Pragma("unroll")                                                     \
        for (int t = 0; t < 4; t++) {                                         \
            uint32_t r_[4];                                                   \
            lds128(r_, (stg) + ST_W + wbase + ((half) * 4 + t) * 1536);       \
            bh[t][0] = r_[0]; bh[t][1] = r_[1];                               \
            bl[t][0] = r_[2]; bl[t][1] = r_[3];                               \
        }                                                                     \
    } while (0)
#define MMA_BURST(half)                                                \
    do {                                                               \
        _Pragma("unroll")                                              \
        for (int t = 0; t < 4; t++) {                                  \
            mma16(acc[0][(half) * 4 + t], ah[0], bh[t][0], bh[t][1]);  \
            mma16(acc[1][(half) * 4 + t], ah[1], bh[t][0], bh[t][1]);  \
        }                                                              \
        _Pragma("unroll")                                              \
        for (int t = 0; t < 4; t++) {                                  \
            mma16(acc[0][(half) * 4 + t], ah[0], bl[t][0], bl[t][1]);  \
            mma16(acc[1][(half) * 4 + t], ah[1], bl[t][0], bl[t][1]);  \
        }                                                              \
        _Pragma("unroll")                                              \
        for (int t = 0; t < 4; t++) {                                  \
            mma16(acc[0][(half) * 4 + t], al[0], bh[t][0], bh[t][1]);  \
            mma16(acc[1][(half) * 4 + t], al[1], bh[t][0], bh[t][1]);  \
        }                                                              \
    } while (0)

    // ---------------- prolog ----------------
    copyW(0, sb + 0 * STAGE);
    asm volatile("cp.async.commit_group;" ::: "memory");
    copyW(1, sb + 1 * STAGE);
    asm volatile("cp.async.commit_group;" ::: "memory");
    {
        float4 v0 = *(const float4*)(xrow);
        float4 v1 = *(const float4*)(xrow + 4);
        stsA(sb + 0 * STAGE, v0, v1);                      // A(0)
    }
    float4 xr0 = *(const float4*)(xrow + BK);              // x(1)
    float4 xr1 = *(const float4*)(xrow + BK + 4);

    asm volatile("cp.async.wait_group 1;" ::: "memory");   // W(0) landed
    __syncthreads();                                       // A(0) + W(0) visible

    for (int kt = 0; kt < NKT; kt++) {
        const uint32_t stg  = sb + (kt % 3) * STAGE;
        const uint32_t stg1 = sb + ((kt + 1) % 3) * STAGE;
        const uint32_t stg2 = sb + ((kt + 2) % 3) * STAGE;

        // fragments for this ktile (this warp's fixed kc = kg)
        LDM_A(stg);
        LDS_B(stg, 0);
        MMA_BURST(0);

        // staging under the tensor burst:
        //   A(kt+1) -> stage kt+1 (visible after this iter's barrier)
        //   W(kt+2) -> stage kt+2 via cp.async (waited next iter)
        if (kt + 1 < NKT) stsA(stg1, xr0, xr1);
        if (kt + 2 < NKT) copyW(kt + 2, stg2);
        if (kt + 2 < NKT) {
            const float* xp = xrow + (kt + 2) * BK;
            xr0 = *(const float4*)(xp);
            xr1 = *(const float4*)(xp + 4);
        }
        asm volatile("cp.async.commit_group;" ::: "memory");

        LDS_B(stg, 1);
        MMA_BURST(1);

        // close the iter: own cp.async for W(kt+1) landed, then make everyone's
        // cp.async + A-STS visible.
        asm volatile("cp.async.wait_group 1;" ::: "memory");
        __syncthreads();
    }

    // -------- epilogue: split-K merge + gate --------
    float* Ls = (float*)smem;        // [128][LLD] logits (reuses stage smem)
    if (kg == 0) {
#pragma unroll
        for (int tm = 0; tm < 2; tm++) {
            int row0 = 32 * wm + 16 * tm + gr;
#pragma unroll
            for (int t = 0; t < 8; t++) {
                int col0 = 64 * wn + 8 * t + 2 * qc;
                Ls[row0 * LLD + col0]           = acc[tm][t][0] * WSCALE_INV;
                Ls[row0 * LLD + col0 + 1]       = acc[tm][t][1] * WSCALE_INV;
                Ls[(row0 + 8) * LLD + col0]     = acc[tm][t][2] * WSCALE_INV;
                Ls[(row0 + 8) * LLD + col0 + 1] = acc[tm][t][3] * WSCALE_INV;
            }
        }
    }
    // zero this CTA's output block (coalesced) meanwhile
    {
        float4 z = make_float4(0.f, 0.f, 0.f, 0.f);
        float4* ob = (float4*)(out + (size_t)m0 * EN);
#pragma unroll
        for (int i = tid; i < BM * EN / 4; i += 512) ob[i] = z;
    }
    __syncthreads();
    if (kg == 1) {
#pragma unroll
        for (int tm = 0; tm < 2; tm++) {
            int row0 = 32 * wm + 16 * tm + gr;
#pragma unroll
            for (int t = 0; t < 8; t++) {
                int col0 = 64 * wn + 8 * t + 2 * qc;
                Ls[row0 * LLD + col0]           += acc[tm][t][0] * WSCALE_INV;
                Ls[row0 * LLD + col0 + 1]       += acc[tm][t][1] * WSCALE_INV;
                Ls[(row0 + 8) * LLD + col0]     += acc[tm][t][2] * WSCALE_INV;
                Ls[(row0 + 8) * LLD + col0 + 1] += acc[tm][t][3] * WSCALE_INV;
            }
        }
    }
    __syncthreads();

    if (tid < BM) {                  // one output row per thread
        const float* Lr = Ls + tid * LLD;
        const float* nz = noise + (size_t)(m0 + tid) * EN;
        float best = -3e38f, second = -3e38f;
        int bi = 0, si = 0;
#pragma unroll 4
        for (int e = 0; e < EN; e++) {
            float z  = Lr[EN + e];
            float sp = fmaxf(z, 0.f) + log1pf(expf(-fabsf(z)));   // accurate softplus
            float w  = Lr[e] + nz[e] * sp;
            if (w > best)        { second = best; si = bi; best = w; bi = e; }
            else if (w > second) { second = w; si = e; }
        }
        float e2  = expf(second - best);
        float inv = 1.f / (1.f + e2);
        float* orow = out + (size_t)(m0 + tid) * EN;
        orow[bi] = inv;
        orow[si] = e2 * inv;
    }
}

extern "C" void kernel_launch(void* const* d_in, const int* in_sizes, int n_in,
                              void* d_out, int out_size) {
    const float* x  = (const float*)d_in[0];
    const float* gw = (const float*)d_in[1];
    const float* nw = (const float*)d_in[2];
    const float* nz = (const float*)d_in[3];
    float* out = (float*)d_out;

    static bool attr_done = false;
    if (!attr_done) {
        cudaFuncSetAttribute(gate_kernel, cudaFuncAttributeMaxDynamicSharedMemorySize,
                             SMEM_TOTAL);
        attr_done = true;
    }

    split_w_kernel<<<(NN * NKT * 8 + 255) / 256, 256>>>(gw, nw);
    gate_kernel<<<16384 / BM, 512, SMEM_TOTAL>>>(x, nz, out);
}